// round 12
// baseline (speedup 1.0000x reference)
#include <cuda_runtime.h>
#include <math.h>
#include <stdint.h>

#define Bsz 256
#define Tsz 512
#define Dsz 256
#define Ksz 256

__device__ float g_xU[Bsz * Tsz * Ksz];   // 128 MB scratch for xU = x@U + b

// ===========================================================================
// Helpers
// ===========================================================================
__device__ __forceinline__ unsigned long long pack2(float lo, float hi) {
    unsigned long long r;
    asm("mov.b64 %0, {%1, %2};" : "=l"(r) : "f"(lo), "f"(hi));
    return r;
}
__device__ __forceinline__ void unpack2(unsigned long long v, float& lo, float& hi) {
    asm("mov.b64 {%0, %1}, %2;" : "=f"(lo), "=f"(hi) : "l"(v));
}
__device__ __forceinline__ void fma2(unsigned long long& acc, unsigned long long h, unsigned long long w) {
    asm("fma.rn.f32x2 %0, %1, %2, %0;" : "+l"(acc) : "l"(h), "l"(w));
}
__device__ __forceinline__ uint32_t f2tf32(float f) {
    uint32_t r;
    asm("cvt.rna.tf32.f32 %0, %1;" : "=r"(r) : "f"(f));
    return r;
}
__device__ __forceinline__ void mma_tf32(float* c, const uint32_t* a, const uint32_t* b) {
    asm("mma.sync.aligned.m16n8k8.row.col.f32.tf32.tf32.f32 "
        "{%0,%1,%2,%3}, {%4,%5,%6,%7}, {%8,%9}, {%0,%1,%2,%3};"
        : "+f"(c[0]), "+f"(c[1]), "+f"(c[2]), "+f"(c[3])
        : "r"(a[0]), "r"(a[1]), "r"(a[2]), "r"(a[3]), "r"(b[0]), "r"(b[1]));
}
__device__ __forceinline__ uint32_t smem_u32(const void* p) {
    uint32_t a;
    asm("{ .reg .u64 t; cvta.to.shared.u64 t, %1; cvt.u32.u64 %0, t; }" : "=r"(a) : "l"(p));
    return a;
}

// ===========================================================================
// Kernel A: xU = X @ U + b   — tf32 tensor cores (unchanged)
// ===========================================================================
__global__ void __launch_bounds__(256) gemm_xu_tc(
    const float* __restrict__ X,
    const float* __restrict__ U,
    const float* __restrict__ bias,
    float* __restrict__ out)
{
    __shared__ float As[128][36];
    __shared__ float Bs[32][132];

    const int tid  = threadIdx.x;
    const int wid  = tid >> 5;
    const int lane = tid & 31;
    const int wm   = (wid & 3) * 32;
    const int wn   = (wid >> 2) * 64;
    const int row0 = blockIdx.y * 128;
    const int col0 = blockIdx.x * 128;

    float acc[2][8][4];
    #pragma unroll
    for (int mt = 0; mt < 2; mt++)
        #pragma unroll
        for (int nt = 0; nt < 8; nt++)
            #pragma unroll
            for (int i = 0; i < 4; i++) acc[mt][nt][i] = 0.0f;

    const int ar = lane >> 2;
    const int ac = lane & 3;
    const int bk = lane & 3;
    const int bn = lane >> 2;

    for (int kb = 0; kb < Dsz; kb += 32) {
        #pragma unroll
        for (int i = 0; i < 4; i++) {
            int lin = tid + i * 256;
            int m = lin >> 3, k = (lin & 7) << 2;
            float4 v = *(const float4*)&X[(size_t)(row0 + m) * Dsz + kb + k];
            v.x = __uint_as_float(f2tf32(v.x));
            v.y = __uint_as_float(f2tf32(v.y));
            v.z = __uint_as_float(f2tf32(v.z));
            v.w = __uint_as_float(f2tf32(v.w));
            *(float4*)&As[m][k] = v;

            int k2 = lin >> 5, n = (lin & 31) << 2;
            float4 u = *(const float4*)&U[(size_t)(kb + k2) * Ksz + col0 + n];
            u.x = __uint_as_float(f2tf32(u.x));
            u.y = __uint_as_float(f2tf32(u.y));
            u.z = __uint_as_float(f2tf32(u.z));
            u.w = __uint_as_float(f2tf32(u.w));
            *(float4*)&Bs[k2][n] = u;
        }
        __syncthreads();

        #pragma unroll
        for (int kc = 0; kc < 4; kc++) {
            const int k0 = kc * 8;
            uint32_t af[2][4];
            #pragma unroll
            for (int mt = 0; mt < 2; mt++) {
                const int mb = wm + mt * 16;
                af[mt][0] = __float_as_uint(As[mb + ar    ][k0 + ac    ]);
                af[mt][1] = __float_as_uint(As[mb + ar + 8][k0 + ac    ]);
                af[mt][2] = __float_as_uint(As[mb + ar    ][k0 + ac + 4]);
                af[mt][3] = __float_as_uint(As[mb + ar + 8][k0 + ac + 4]);
            }
            #pragma unroll
            for (int nt = 0; nt < 8; nt++) {
                uint32_t bf[2];
                const int nb = wn + nt * 8 + bn;
                bf[0] = __float_as_uint(Bs[k0 + bk    ][nb]);
                bf[1] = __float_as_uint(Bs[k0 + bk + 4][nb]);
                mma_tf32(acc[0][nt], af[0], bf);
                mma_tf32(acc[1][nt], af[1], bf);
            }
        }
        __syncthreads();
    }

    #pragma unroll
    for (int nt = 0; nt < 8; nt++) {
        const int cb = col0 + wn + nt * 8 + 2 * (lane & 3);
        float2 bb = *(const float2*)&bias[cb];
        #pragma unroll
        for (int mt = 0; mt < 2; mt++) {
            const int r = row0 + wm + mt * 16 + (lane >> 2);
            float2 o0 = { acc[mt][nt][0] + bb.x, acc[mt][nt][1] + bb.y };
            float2 o1 = { acc[mt][nt][2] + bb.x, acc[mt][nt][3] + bb.y };
            *(float2*)&out[(size_t)r       * Ksz + cb] = o0;
            *(float2*)&out[(size_t)(r + 8) * Ksz + cb] = o1;
        }
    }
}

// ===========================================================================
// Kernel B (R12): recurrence. 64 clusters x 2 CTAs x 512 threads; 4 rows.
// CTA rank owns cols [128*rank, +128) with FULL d=256 (no reduction).
// Thread (c 0..127, q 0..3): lane = c_sub*4 + q, c = w*8 + c_sub.
// W: 32 ull regs/thread, d-parity pairs (w2j, w2j+1).
// h layout: [buf][q-chunk stride 260][j = d-pair][dp + 2r] -> one LDS.128 =
//   (d-even, d-odd) x (row r, row r+1); q-lanes hit disjoint banks (260%32=4).
// Exchange: q0 threads store 4 h floats local+peer (plain st.shared::cluster);
// non-q0 threads arrive at the cluster barrier EARLY (right after last read).
// ===========================================================================
#define HCH 260                     // floats per q-chunk (64 d x 4 rows + pad 4)
#define HBUF (4 * HCH)              // 1040 floats per buffer

__global__ void __launch_bounds__(512, 1) __cluster_dims__(2, 1, 1)
rnn_rec12_kernel(const float* __restrict__ xU,
                 const float* __restrict__ W,
                 float* __restrict__ out)
{
    __shared__ alignas(16) float hb[2][HBUF];   // 8.3 KB

    const int tid  = threadIdx.x;
    const int w    = tid >> 5;                  // 0..15
    const int lane = tid & 31;
    const int q    = lane & 3;                  // d-quarter (64 d)
    const int c    = w * 8 + (lane >> 2);       // column within CTA 0..127

    uint32_t rank;
    asm("mov.u32 %0, %%cluster_ctarank;" : "=r"(rank));
    const uint32_t peer = rank ^ 1u;
    const int cg = ((int)rank << 7) + c;        // global column 0..255
    const int b0 = blockIdx.x >> 1 << 2;        // 4 batch rows per cluster

    // W slice, d-parity packed: Wp[j] = (W[64q+2j][cg], W[64q+2j+1][cg])
    unsigned long long Wp[32];
    #pragma unroll
    for (int j = 0; j < 32; j++) {
        float w0 = W[(size_t)(q * 64 + 2 * j    ) * Ksz + cg];
        float w1 = W[(size_t)(q * 64 + 2 * j + 1) * Ksz + cg];
        Wp[j] = pack2(w0, w1);
    }

    // zero h buffers
    for (int i = tid; i < 2 * HBUF; i += 512) ((float*)hb)[i] = 0.0f;
    __syncthreads();
    asm volatile("barrier.cluster.arrive.aligned;" ::: "memory");
    asm volatile("barrier.cluster.wait.aligned;"   ::: "memory");

    // read base: this thread's q-chunk; write slots: element (d=cg, r) at
    // 260*(cg>>6) + 8*((cg&63)>>1) + (cg&1) + 2r   (4 floats, stride 2 words)
    uint32_t rdL[2];
    rdL[0] = smem_u32(&hb[0][q * HCH]);
    rdL[1] = smem_u32(&hb[1][q * HCH]);
    const int wslot = (cg >> 6) * HCH + ((cg & 63) >> 1) * 8 + (cg & 1);
    uint32_t wrL[2], wrP[2];
    #pragma unroll
    for (int p = 0; p < 2; p++) {
        uint32_t a = smem_u32(&hb[p][wslot]);
        wrL[p] = a;
        asm("mapa.shared::cluster.u32 %0, %1, %2;" : "=r"(wrP[p]) : "r"(a), "r"(peer));
    }

    // xu pointers (q0 threads consume; rows b0..b0+3, col cg)
    const float* xp0 = xU + (size_t)(b0 + 0) * Tsz * Ksz + cg;
    const float* xp1 = xU + (size_t)(b0 + 1) * Tsz * Ksz + cg;
    const float* xp2 = xU + (size_t)(b0 + 2) * Tsz * Ksz + cg;
    const float* xp3 = xU + (size_t)(b0 + 3) * Tsz * Ksz + cg;
    float xu0 = 0.f, xu1 = 0.f, xu2 = 0.f, xu3 = 0.f;
    if (q == 0) { xu0 = xp0[0]; xu1 = xp1[0]; xu2 = xp2[0]; xu3 = xp3[0]; }

    float hv0 = 0.f, hv1 = 0.f, hv2 = 0.f, hv3 = 0.f;

    for (int t = 0; t < Tsz; t++) {
        const uint32_t rb = rdL[t & 1];

        // 32 j-iters x (2 LDS.128 + 4 FMA2): accs a0..a3 = rows (f32x2 = d-parity)
        unsigned long long a0 = 0ull, a1 = 0ull, a2 = 0ull, a3 = 0ull;
        #pragma unroll
        for (int j = 0; j < 32; j++) {
            uint32_t x0, x1, x2, x3, y0, y1, y2, y3;
            asm("ld.shared.v4.b32 {%0,%1,%2,%3}, [%4];"
                : "=r"(x0), "=r"(x1), "=r"(x2), "=r"(x3) : "r"(rb + j * 32));
            asm("ld.shared.v4.b32 {%0,%1,%2,%3}, [%4];"
                : "=r"(y0), "=r"(y1), "=r"(y2), "=r"(y3) : "r"(rb + j * 32 + 16));
            unsigned long long h01r0 = ((unsigned long long)x1 << 32) | x0;  // (dpair, r0)
            unsigned long long h01r1 = ((unsigned long long)x3 << 32) | x2;  // (dpair, r1)
            unsigned long long h01r2 = ((unsigned long long)y1 << 32) | y0;  // (dpair, r2)
            unsigned long long h01r3 = ((unsigned long long)y3 << 32) | y2;  // (dpair, r3)
            fma2(a0, h01r0, Wp[j]);
            fma2(a1, h01r1, Wp[j]);
            fma2(a2, h01r2, Wp[j]);
            fma2(a3, h01r3, Wp[j]);
        }

        // fold d-parity; shfl-reduce over q (lane bits 0-1)
        float e, o;
        unpack2(a0, e, o); float s0 = e + o;
        unpack2(a1, e, o); float s1 = e + o;
        unpack2(a2, e, o); float s2 = e + o;
        unpack2(a3, e, o); float s3 = e + o;
        s0 += __shfl_xor_sync(0xffffffffu, s0, 1);
        s1 += __shfl_xor_sync(0xffffffffu, s1, 1);
        s2 += __shfl_xor_sync(0xffffffffu, s2, 1);
        s3 += __shfl_xor_sync(0xffffffffu, s3, 1);
        s0 += __shfl_xor_sync(0xffffffffu, s0, 2);
        s1 += __shfl_xor_sync(0xffffffffu, s1, 2);
        s2 += __shfl_xor_sync(0xffffffffu, s2, 2);
        s3 += __shfl_xor_sync(0xffffffffu, s3, 2);

        const int wr = (t + 1 < Tsz);
        const int pn = (t + 1) & 1;
        if (q == 0) {
            s0 += xu0; s1 += xu1; s2 += xu2; s3 += xu3;
            {
                size_t off = (size_t)(wr ? t + 1 : t) * Ksz;
                xu0 = xp0[off]; xu1 = xp1[off]; xu2 = xp2[off]; xu3 = xp3[off];
            }
            hv0 = tanhf(s0); hv1 = tanhf(s1); hv2 = tanhf(s2); hv3 = tanhf(s3);

            if (wr) {
                // 4 floats at stride 2 words (8 bytes)
                asm volatile(
                    "st.shared.f32 [%0], %1;  st.shared.f32 [%0+8], %2;"
                    "st.shared.f32 [%0+16], %3; st.shared.f32 [%0+24], %4;"
                    :: "r"(wrL[pn]), "f"(hv0), "f"(hv1), "f"(hv2), "f"(hv3) : "memory");
                asm volatile(
                    "st.shared::cluster.f32 [%0], %1;  st.shared::cluster.f32 [%0+8], %2;"
                    "st.shared::cluster.f32 [%0+16], %3; st.shared::cluster.f32 [%0+24], %4;"
                    :: "r"(wrP[pn]), "f"(hv0), "f"(hv1), "f"(hv2), "f"(hv3) : "memory");
            }
        }
        // arrive (release: orders the q0 stores); non-q0 threads reach this
        // right after their reads/shfls -> peer's wait chains on q0 tail only
        asm volatile("barrier.cluster.arrive.aligned;" ::: "memory");
        asm volatile("barrier.cluster.wait.aligned;"   ::: "memory");
    }

    if (q == 0) {
        out[(size_t)(b0 + 0) * Ksz + cg] = hv0;
        out[(size_t)(b0 + 1) * Ksz + cg] = hv1;
        out[(size_t)(b0 + 2) * Ksz + cg] = hv2;
        out[(size_t)(b0 + 3) * Ksz + cg] = hv3;
    }
}

// ===========================================================================
// Launch
// ===========================================================================
extern "C" void kernel_launch(void* const* d_in, const int* in_sizes, int n_in,
                              void* d_out, int out_size)
{
    const float* x    = (const float*)d_in[0];   // [256, 512, 256]
    const float* U    = (const float*)d_in[1];   // [256, 256]
    const float* W    = (const float*)d_in[2];   // [256, 256]
    const float* bias = (const float*)d_in[3];   // [256]
    float* out        = (float*)d_out;           // [256, 1, 256]

    float* xU;
    cudaGetSymbolAddress((void**)&xU, g_xU);

    dim3 gridA(Ksz / 128, (Bsz * Tsz) / 128);    // (2, 1024)
    gemm_xu_tc<<<gridA, 256>>>(x, U, bias, xU);

    rnn_rec12_kernel<<<(Bsz / 4) * 2, 512>>>(xU, W, out);
}

// round 13
// speedup vs baseline: 1.5692x; 1.5692x over previous
#include <cuda_runtime.h>
#include <math.h>
#include <stdint.h>

#define Bsz 256
#define Tsz 512
#define Dsz 256
#define Ksz 256

__device__ float g_xU[Bsz * Tsz * Ksz];   // 128 MB scratch for xU = x@U + b

// ===========================================================================
// Helpers
// ===========================================================================
__device__ __forceinline__ unsigned long long pack2(float lo, float hi) {
    unsigned long long r;
    asm("mov.b64 %0, {%1, %2};" : "=l"(r) : "f"(lo), "f"(hi));
    return r;
}
__device__ __forceinline__ void unpack2(unsigned long long v, float& lo, float& hi) {
    asm("mov.b64 {%0, %1}, %2;" : "=f"(lo), "=f"(hi) : "l"(v));
}
__device__ __forceinline__ void fma2(unsigned long long& acc, unsigned long long h, unsigned long long w) {
    asm("fma.rn.f32x2 %0, %1, %2, %0;" : "+l"(acc) : "l"(h), "l"(w));
}
__device__ __forceinline__ unsigned long long add2v(unsigned long long a, unsigned long long b) {
    unsigned long long r;
    asm("add.rn.f32x2 %0, %1, %2;" : "=l"(r) : "l"(a), "l"(b));
    return r;
}
__device__ __forceinline__ uint32_t f2tf32(float f) {
    uint32_t r;
    asm("cvt.rna.tf32.f32 %0, %1;" : "=r"(r) : "f"(f));
    return r;
}
__device__ __forceinline__ void mma_tf32(float* c, const uint32_t* a, const uint32_t* b) {
    asm("mma.sync.aligned.m16n8k8.row.col.f32.tf32.tf32.f32 "
        "{%0,%1,%2,%3}, {%4,%5,%6,%7}, {%8,%9}, {%0,%1,%2,%3};"
        : "+f"(c[0]), "+f"(c[1]), "+f"(c[2]), "+f"(c[3])
        : "r"(a[0]), "r"(a[1]), "r"(a[2]), "r"(a[3]), "r"(b[0]), "r"(b[1]));
}
__device__ __forceinline__ uint32_t smem_u32(const void* p) {
    uint32_t a;
    asm("{ .reg .u64 t; cvta.to.shared.u64 t, %1; cvt.u32.u64 %0, t; }" : "=r"(a) : "l"(p));
    return a;
}

// ===========================================================================
// Kernel A: xU = X @ U + b   — tf32 tensor cores (unchanged)
// ===========================================================================
__global__ void __launch_bounds__(256) gemm_xu_tc(
    const float* __restrict__ X,
    const float* __restrict__ U,
    const float* __restrict__ bias,
    float* __restrict__ out)
{
    __shared__ float As[128][36];
    __shared__ float Bs[32][132];

    const int tid  = threadIdx.x;
    const int wid  = tid >> 5;
    const int lane = tid & 31;
    const int wm   = (wid & 3) * 32;
    const int wn   = (wid >> 2) * 64;
    const int row0 = blockIdx.y * 128;
    const int col0 = blockIdx.x * 128;

    float acc[2][8][4];
    #pragma unroll
    for (int mt = 0; mt < 2; mt++)
        #pragma unroll
        for (int nt = 0; nt < 8; nt++)
            #pragma unroll
            for (int i = 0; i < 4; i++) acc[mt][nt][i] = 0.0f;

    const int ar = lane >> 2;
    const int ac = lane & 3;
    const int bk = lane & 3;
    const int bn = lane >> 2;

    for (int kb = 0; kb < Dsz; kb += 32) {
        #pragma unroll
        for (int i = 0; i < 4; i++) {
            int lin = tid + i * 256;
            int m = lin >> 3, k = (lin & 7) << 2;
            float4 v = *(const float4*)&X[(size_t)(row0 + m) * Dsz + kb + k];
            v.x = __uint_as_float(f2tf32(v.x));
            v.y = __uint_as_float(f2tf32(v.y));
            v.z = __uint_as_float(f2tf32(v.z));
            v.w = __uint_as_float(f2tf32(v.w));
            *(float4*)&As[m][k] = v;

            int k2 = lin >> 5, n = (lin & 31) << 2;
            float4 u = *(const float4*)&U[(size_t)(kb + k2) * Ksz + col0 + n];
            u.x = __uint_as_float(f2tf32(u.x));
            u.y = __uint_as_float(f2tf32(u.y));
            u.z = __uint_as_float(f2tf32(u.z));
            u.w = __uint_as_float(f2tf32(u.w));
            *(float4*)&Bs[k2][n] = u;
        }
        __syncthreads();

        #pragma unroll
        for (int kc = 0; kc < 4; kc++) {
            const int k0 = kc * 8;
            uint32_t af[2][4];
            #pragma unroll
            for (int mt = 0; mt < 2; mt++) {
                const int mb = wm + mt * 16;
                af[mt][0] = __float_as_uint(As[mb + ar    ][k0 + ac    ]);
                af[mt][1] = __float_as_uint(As[mb + ar + 8][k0 + ac    ]);
                af[mt][2] = __float_as_uint(As[mb + ar    ][k0 + ac + 4]);
                af[mt][3] = __float_as_uint(As[mb + ar + 8][k0 + ac + 4]);
            }
            #pragma unroll
            for (int nt = 0; nt < 8; nt++) {
                uint32_t bf[2];
                const int nb = wn + nt * 8 + bn;
                bf[0] = __float_as_uint(Bs[k0 + bk    ][nb]);
                bf[1] = __float_as_uint(Bs[k0 + bk + 4][nb]);
                mma_tf32(acc[0][nt], af[0], bf);
                mma_tf32(acc[1][nt], af[1], bf);
            }
        }
        __syncthreads();
    }

    #pragma unroll
    for (int nt = 0; nt < 8; nt++) {
        const int cb = col0 + wn + nt * 8 + 2 * (lane & 3);
        float2 bb = *(const float2*)&bias[cb];
        #pragma unroll
        for (int mt = 0; mt < 2; mt++) {
            const int r = row0 + wm + mt * 16 + (lane >> 2);
            float2 o0 = { acc[mt][nt][0] + bb.x, acc[mt][nt][1] + bb.y };
            float2 o1 = { acc[mt][nt][2] + bb.x, acc[mt][nt][3] + bb.y };
            *(float2*)&out[(size_t)r       * Ksz + cb] = o0;
            *(float2*)&out[(size_t)(r + 8) * Ksz + cb] = o1;
        }
    }
}

// ===========================================================================
// Kernel B (R13): recurrence. 64 clusters x 2 CTAs x 512 threads; 4 rows.
// KEY: each h byte loaded from smem feeds 4 columns from registers (NC=4),
// cutting crossbar bytes 4x vs all prior rounds (the measured bottleneck).
// Thread (colgroup cq = w*2 + lane>>4, q = lane&15): owns cols cq*4..+3,
// d slice {q, 16+q, ..., 240+q} (16 d), all 4 rows.
// h layout: [buf][d][4 rows] (16B/d). LDS.128 per d: 16 distinct addresses
// per warp covering all 32 banks twice -> 2 wf (4 wf worst case, no dedup).
// Reduction over 16 q-lanes: 4-round recursive-halving shfl butterfly; after
// it EVERY lane owns one (row, col) output -> tanh/xu/store fully distributed.
// Sync: plain st.shared::cluster h broadcast + full 2-CTA cluster barrier.
// ===========================================================================
__global__ void __launch_bounds__(512, 1) __cluster_dims__(2, 1, 1)
rnn_rec13_kernel(const float* __restrict__ xU,
                 const float* __restrict__ W,
                 float* __restrict__ out)
{
    __shared__ alignas(16) float hb[2][Ksz][4];   // [buf][d][row] = 8 KB

    const int tid  = threadIdx.x;
    const int w    = tid >> 5;                  // 0..15
    const int lane = tid & 31;
    const int q    = lane & 15;                 // d-slice id
    const int c2   = lane >> 4;                 // 0..1
    const int cq   = w * 2 + c2;                // colgroup 0..31 (4 cols each)

    uint32_t rank;
    asm("mov.u32 %0, %%cluster_ctarank;" : "=r"(rank));
    const uint32_t peer = rank ^ 1u;
    const int cbase = ((int)rank << 7) + cq * 4;     // first of 4 owned cols
    const int b0 = (blockIdx.x >> 1) * 4;            // 4 batch rows per cluster

    // Output identity after reduction: this lane owns (row, col):
    const int row    = 2 * (q & 1) + ((q >> 1) & 1);
    const int colofs = 2 * ((q >> 2) & 1) + ((q >> 3) & 1);
    const int cg     = cbase + colofs;

    // W pack: Wp[j][cp] = (W[16j+q][cbase+2cp], W[16j+q][cbase+2cp+1])
    unsigned long long Wp[16][2];
    #pragma unroll
    for (int j = 0; j < 16; j++) {
        const float* wr = &W[(size_t)(16 * j + q) * Ksz + cbase];
        Wp[j][0] = pack2(wr[0], wr[1]);
        Wp[j][1] = pack2(wr[2], wr[3]);
    }

    // zero h buffers
    for (int i = tid; i < 2 * Ksz * 4; i += 512) ((float*)hb)[i] = 0.0f;
    __syncthreads();
    asm volatile("barrier.cluster.arrive.aligned;" ::: "memory");
    asm volatile("barrier.cluster.wait.aligned;"   ::: "memory");

    // read base: &hb[buf][q][0]; j advances by 16 d = 256 bytes
    uint32_t rdL[2] = { smem_u32(&hb[0][q][0]), smem_u32(&hb[1][q][0]) };
    // write slot: &hb[p][cg][row] local + peer
    uint32_t wrL[2], wrP[2];
    #pragma unroll
    for (int p = 0; p < 2; p++) {
        uint32_t a = smem_u32(&hb[p][cg][row]);
        wrL[p] = a;
        asm("mapa.shared::cluster.u32 %0, %1, %2;" : "=r"(wrP[p]) : "r"(a), "r"(peer));
    }

    // xu pointer for this lane's (row, col)
    const float* xp = xU + (size_t)(b0 + row) * Tsz * Ksz + cg;
    float xu = xp[0];
    float hv = 0.0f;

    for (int t = 0; t < Tsz; t++) {
        const uint32_t rb = rdL[t & 1];

        // 16 j-iters: LDS.128 (h[d][r0..r3]) + 4 dup-packs + 8 FMA2
        unsigned long long a[2][4];
        #pragma unroll
        for (int cp = 0; cp < 2; cp++)
            #pragma unroll
            for (int r = 0; r < 4; r++) a[cp][r] = 0ull;

        #pragma unroll
        for (int j = 0; j < 16; j++) {
            uint32_t h0, h1, h2, h3;
            asm("ld.shared.v4.b32 {%0,%1,%2,%3}, [%4];"
                : "=r"(h0), "=r"(h1), "=r"(h2), "=r"(h3) : "r"(rb + j * 256));
            unsigned long long hd0 = ((unsigned long long)h0 << 32) | h0;
            unsigned long long hd1 = ((unsigned long long)h1 << 32) | h1;
            unsigned long long hd2 = ((unsigned long long)h2 << 32) | h2;
            unsigned long long hd3 = ((unsigned long long)h3 << 32) | h3;
            fma2(a[0][0], hd0, Wp[j][0]); fma2(a[1][0], hd0, Wp[j][1]);
            fma2(a[0][1], hd1, Wp[j][0]); fma2(a[1][1], hd1, Wp[j][1]);
            fma2(a[0][2], hd2, Wp[j][0]); fma2(a[1][2], hd2, Wp[j][1]);
            fma2(a[0][3], hd3, Wp[j][0]); fma2(a[1][3], hd3, Wp[j][1]);
        }

        // ---- recursive-halving butterfly over the 16 q-lanes ----
        const unsigned b0q = q & 1, b1q = q & 2, b2q = q & 4;
        // Round 1 (mask 1): keep rows {0,1} if bit0=0 else {2,3}
        unsigned long long r1[2][2];
        #pragma unroll
        for (int cp = 0; cp < 2; cp++)
            #pragma unroll
            for (int k = 0; k < 2; k++) {
                unsigned long long send = b0q ? a[cp][k] : a[cp][2 + k];
                unsigned long long keep = b0q ? a[cp][2 + k] : a[cp][k];
                unsigned long long got  = __shfl_xor_sync(0xffffffffu, send, 1);
                r1[cp][k] = add2v(keep, got);
            }
        // Round 2 (mask 2): keep k=0 if bit1=0 else k=1
        unsigned long long r2[2];
        #pragma unroll
        for (int cp = 0; cp < 2; cp++) {
            unsigned long long send = b1q ? r1[cp][0] : r1[cp][1];
            unsigned long long keep = b1q ? r1[cp][1] : r1[cp][0];
            unsigned long long got  = __shfl_xor_sync(0xffffffffu, send, 2);
            r2[cp] = add2v(keep, got);
        }
        // Round 3 (mask 4): keep cp=0 if bit2=0 else cp=1
        {
            unsigned long long send = b2q ? r2[0] : r2[1];
            unsigned long long keep = b2q ? r2[1] : r2[0];
            unsigned long long got  = __shfl_xor_sync(0xffffffffu, send, 4);
            r2[0] = add2v(keep, got);
        }
        // Round 4 (mask 8): complete 16-lane sum
        {
            unsigned long long got = __shfl_xor_sync(0xffffffffu, r2[0], 8);
            r2[0] = add2v(r2[0], got);
        }
        float lo, hi;
        unpack2(r2[0], lo, hi);
        float s = (q & 8) ? hi : lo;

        s += xu;
        const int wrS = (t + 1 < Tsz);
        xu = xp[(size_t)(wrS ? t + 1 : t) * Ksz];   // prefetch next step
        hv = tanhf(s);

        if (wrS) {
            const int pn = (t + 1) & 1;
            asm volatile("st.shared.f32 [%0], %1;" :: "r"(wrL[pn]), "f"(hv) : "memory");
            asm volatile("st.shared::cluster.f32 [%0], %1;" :: "r"(wrP[pn]), "f"(hv) : "memory");
        }
        asm volatile("barrier.cluster.arrive.aligned;" ::: "memory");
        asm volatile("barrier.cluster.wait.aligned;"   ::: "memory");
    }

    out[(size_t)(b0 + row) * Ksz + cg] = hv;
}

// ===========================================================================
// Launch
// ===========================================================================
extern "C" void kernel_launch(void* const* d_in, const int* in_sizes, int n_in,
                              void* d_out, int out_size)
{
    const float* x    = (const float*)d_in[0];   // [256, 512, 256]
    const float* U    = (const float*)d_in[1];   // [256, 256]
    const float* W    = (const float*)d_in[2];   // [256, 256]
    const float* bias = (const float*)d_in[3];   // [256]
    float* out        = (float*)d_out;           // [256, 1, 256]

    float* xU;
    cudaGetSymbolAddress((void**)&xU, g_xU);

    dim3 gridA(Ksz / 128, (Bsz * Tsz) / 128);    // (2, 1024)
    gemm_xu_tc<<<gridA, 256>>>(x, U, bias, xU);

    rnn_rec13_kernel<<<(Bsz / 4) * 2, 512>>>(xU, W, out);
}